// round 15
// baseline (speedup 1.0000x reference)
#include <cuda_runtime.h>
#include <cuda_fp16.h>
#include <math.h>
#include <stdint.h>

#define BATCH 4
#define SEQ 64
#define PAST 2048
#define TTOT 2112
#define HIDDEN 2048
#define NQ 16
#define NKV 4
#define HDIM 128
#define INTER 8192
#define VOCAB 32000
#define ROWS 256
#define EPS 1e-6f

#define LOGITS_ELEMS (ROWS * VOCAB)
#define GATHERED_ELEMS (ROWS * HIDDEN)
#define PRESENT_OFF (LOGITS_ELEMS + GATHERED_ELEMS)

// ---------------------------------------------------------------------------
// Scratch (device globals)
// ---------------------------------------------------------------------------
__device__ float g_hs[ROWS * HIDDEN];
__device__ float g_normed[ROWS * 2 * HIDDEN];
__device__ float g_qkv[ROWS * 3072];
__device__ float g_attn[ROWS * NQ * HDIM];
__device__ float g_hn[ROWS * HIDDEN];
__device__ float g_gu[ROWS * 2 * INTER];
__device__ float g_act[ROWS * INTER];
__device__ float g_fn[ROWS * HIDDEN];
__device__ float g_part[8 * ROWS * 3072];
__device__ float g_ml[6 * ROWS * NQ * 2];

// ---------------------------------------------------------------------------
// Helpers
// ---------------------------------------------------------------------------
__device__ __forceinline__ uint32_t smem_u32(const void* p) {
    uint32_t a;
    asm("{ .reg .u64 t; cvta.to.shared.u64 t, %1; cvt.u32.u64 %0, t; }"
        : "=r"(a) : "l"(p));
    return a;
}
__device__ __forceinline__ uint32_t f2h2(float lo, float hi) {
    uint32_t r;
    asm("cvt.rn.f16x2.f32 %0, %1, %2;" : "=r"(r) : "f"(hi), "f"(lo));
    return r;
}
__device__ __forceinline__ void cpasync16(uint32_t s, const float* g) {
    asm volatile("cp.async.cg.shared.global [%0], [%1], 16;" :: "r"(s), "l"(g));
}
#define CP_COMMIT() asm volatile("cp.async.commit_group;" ::: "memory")
#define CP_WAIT_1() asm volatile("cp.async.wait_group 1;" ::: "memory")
#define CP_WAIT_0() asm volatile("cp.async.wait_group 0;" ::: "memory")

__device__ __forceinline__ void ldsm_x4(uint32_t* r, uint32_t addr) {
    asm volatile("ldmatrix.sync.aligned.m8n8.x4.shared.b16 {%0,%1,%2,%3}, [%4];"
                 : "=r"(r[0]), "=r"(r[1]), "=r"(r[2]), "=r"(r[3]) : "r"(addr));
}
__device__ __forceinline__ void ldsm_x2t(uint32_t* r, uint32_t addr) {
    asm volatile("ldmatrix.sync.aligned.m8n8.x2.trans.shared.b16 {%0,%1}, [%2];"
                 : "=r"(r[0]), "=r"(r[1]) : "r"(addr));
}
__device__ __forceinline__ void mma_f16(float* c, const uint32_t* a, const uint32_t* b) {
    asm volatile(
        "mma.sync.aligned.m16n8k16.row.col.f32.f16.f16.f32 "
        "{%0,%1,%2,%3}, {%4,%5,%6,%7}, {%8,%9}, {%0,%1,%2,%3};"
        : "+f"(c[0]), "+f"(c[1]), "+f"(c[2]), "+f"(c[3])
        : "r"(a[0]), "r"(a[1]), "r"(a[2]), "r"(a[3]), "r"(b[0]), "r"(b[1]));
}

__device__ __forceinline__ float block_sum(float v) {
    __shared__ float sh[8];
    __shared__ float total;
    int tid = threadIdx.x;
#pragma unroll
    for (int o = 16; o > 0; o >>= 1) v += __shfl_xor_sync(0xffffffffu, v, o);
    if ((tid & 31) == 0) sh[tid >> 5] = v;
    __syncthreads();
    if (tid == 0) {
        float s = 0.f;
#pragma unroll
        for (int i = 0; i < 8; i++) s += sh[i];
        total = s;
    }
    __syncthreads();
    float r = total;
    __syncthreads();
    return r;
}
__device__ __forceinline__ float block_max(float v) {
    __shared__ float sh[8];
    __shared__ float total;
    int tid = threadIdx.x;
#pragma unroll
    for (int o = 16; o > 0; o >>= 1) v = fmaxf(v, __shfl_xor_sync(0xffffffffu, v, o));
    if ((tid & 31) == 0) sh[tid >> 5] = v;
    __syncthreads();
    if (tid == 0) {
        float s = -INFINITY;
#pragma unroll
        for (int i = 0; i < 8; i++) s = fmaxf(s, sh[i]);
        total = s;
    }
    __syncthreads();
    float r = total;
    __syncthreads();
    return r;
}

// ---------------------------------------------------------------------------
// fp16 GEMM core: 128x128 C tile, 256 threads, m16n8k16 + ldmatrix.
// cp.async fp32 staging ring (2 stages) -> convert (LDS+cvt+STS fp16, one
// stage ahead) -> consume. fp16 bufs: A [128][40h], B [32][136h].
// fp32 staging: A [128][32], B [32][128].
// ---------------------------------------------------------------------------
#define HA_BYTES (128 * 80)
#define HB_BYTES (32 * 272)
#define HSTAGE (HA_BYTES + HB_BYTES)       // 18944
#define STG_OFF (2 * HSTAGE)               // fp32 staging base
#define STG_STAGE 32768                    // 16KB A + 16KB B
#define GSMEM (2 * HSTAGE + 2 * STG_STAGE) // 103424

template <int EPI>
__device__ __forceinline__ void gemm_core(
    const float* __restrict__ A, int lda, int mBase,
    const float* __restrict__ B,
    float* __restrict__ C, const float* __restrict__ Aux,
    int kLen, int ldB, int nB, int ldC, int nC)
{
    extern __shared__ char smc[];
    const uint32_t smBase = smem_u32(smc);

    const int tid = threadIdx.x;
    const int lane = tid & 31;
    const int wid = tid >> 5;
    const int warpM = wid & 1;
    const int warpN = wid >> 1;
    const int gid = lane >> 2;
    const int tig = lane & 3;

    float acc[4][4][4];
#pragma unroll
    for (int a = 0; a < 4; a++)
#pragma unroll
        for (int b = 0; b < 4; b++)
#pragma unroll
            for (int c = 0; c < 4; c++) acc[a][b][c] = 0.f;

    int aRow[4], aKc[4], bKr[4], bNc[4];
#pragma unroll
    for (int i = 0; i < 4; i++) {
        int fi = tid + 256 * i;
        aRow[i] = fi >> 3;  aKc[i] = (fi & 7) << 2;
        bKr[i] = fi >> 5;   bNc[i] = (fi & 31) << 2;
    }

    const uint32_t aLane = smBase +
        (uint32_t)((warpM * 64 + (lane & 15)) * 80 + ((lane >> 4) << 4));
    const uint32_t bLane = smBase + HA_BYTES +
        (uint32_t)((lane & 15) * 272 + warpN * 64);

    const int nStg = kLen >> 5;

    // producer: cp.async stage s into staging slot s&1
    auto issue = [&](int s) {
        const int k0 = s * 32;
        const uint32_t st = smBase + STG_OFF + (uint32_t)(s & 1) * STG_STAGE;
#pragma unroll
        for (int j = 0; j < 4; j++) {
            cpasync16(st + (uint32_t)(aRow[j] * 32 + aKc[j]) * 4u,
                      A + (size_t)(mBase + aRow[j]) * lda + k0 + aKc[j]);
            cpasync16(st + 16384u + (uint32_t)(bKr[j] * 128 + bNc[j]) * 4u,
                      B + (size_t)(k0 + bKr[j]) * ldB + nB + bNc[j]);
        }
        CP_COMMIT();
    };
    // convert stage s: staging slot s&1 -> fp16 buf s&1
    auto convert = [&](int s) {
        const char* st = smc + STG_OFF + (s & 1) * STG_STAGE;
        char* hb = smc + (s & 1) * HSTAGE;
#pragma unroll
        for (int j = 0; j < 4; j++) {
            float4 v = *(const float4*)(st + (aRow[j] * 32 + aKc[j]) * 4);
            *(uint2*)(hb + aRow[j] * 80 + aKc[j] * 2) =
                make_uint2(f2h2(v.x, v.y), f2h2(v.z, v.w));
            float4 w = *(const float4*)(st + 16384 + (bKr[j] * 128 + bNc[j]) * 4);
            *(uint2*)(hb + HA_BYTES + bKr[j] * 272 + bNc[j] * 2) =
                make_uint2(f2h2(w.x, w.y), f2h2(w.z, w.w));
        }
    };

    issue(0);
    issue(1);
    CP_WAIT_1();
    __syncthreads();
    convert(0);
    __syncthreads();

    for (int i = 0; i < nStg; i++) {
        if (i + 2 < nStg) issue(i + 2);
        const uint32_t bufOff = (uint32_t)(i & 1) * HSTAGE;
#pragma unroll
        for (int g = 0; g < 2; g++) {
            uint32_t aG = aLane + bufOff + g * 32;
            uint32_t bG = bLane + bufOff + (uint32_t)g * (16 * 272);
            uint32_t bf[4][2];
#pragma unroll
            for (int nj = 0; nj < 4; nj++) ldsm_x2t(bf[nj], bG + nj * 16);
#pragma unroll
            for (int mi = 0; mi < 4; mi++) {
                uint32_t af[4];
                ldsm_x4(af, aG + mi * 1280);
#pragma unroll
                for (int nj = 0; nj < 4; nj++)
                    mma_f16(acc[mi][nj], af, bf[nj]);
            }
        }
        if (i + 1 < nStg) {
            if (i + 2 < nStg) { CP_WAIT_1(); } else { CP_WAIT_0(); }
            __syncthreads();     // staging(i+1) visible; fp16 buf (i+1)&1 free
            convert(i + 1);
        }
        __syncthreads();
    }

#pragma unroll
    for (int mi = 0; mi < 4; mi++) {
        int row = mBase + warpM * 64 + mi * 16 + gid;
#pragma unroll
        for (int nj = 0; nj < 4; nj++) {
            int col = nC + warpN * 32 + nj * 8 + tig * 2;
            float2 v0 = make_float2(acc[mi][nj][0], acc[mi][nj][1]);
            float2 v1 = make_float2(acc[mi][nj][2], acc[mi][nj][3]);
            size_t o0 = (size_t)row * ldC + col;
            size_t o1 = (size_t)(row + 8) * ldC + col;
            if (EPI == 1) {
                float2 x0 = *reinterpret_cast<const float2*>(Aux + o0);
                float2 x1 = *reinterpret_cast<const float2*>(Aux + o1);
                v0.x += x0.x; v0.y += x0.y;
                v1.x += x1.x; v1.y += x1.y;
            }
            *reinterpret_cast<float2*>(C + o0) = v0;
            *reinterpret_cast<float2*>(C + o1) = v1;
        }
    }
}

template <int EPI>
__global__ void __launch_bounds__(256, 2) tgemm(
    const float* __restrict__ A, const float* __restrict__ B,
    float* __restrict__ C, const float* __restrict__ Aux, int K, int ldB, int ldC)
{
    gemm_core<EPI>(A, K, blockIdx.y * 128, B, C, Aux, K, ldB, blockIdx.x * 128,
                   ldC, blockIdx.x * 128);
}

// lm-head: m = blockIdx.x (2), n = blockIdx.y (250): B-tile-sharing CTAs adjacent
__global__ void __launch_bounds__(256, 2) tgemm_lm(
    const float* __restrict__ A, const float* __restrict__ B,
    float* __restrict__ C, int K, int ldB, int ldC)
{
    gemm_core<0>(A, K, blockIdx.x * 128, B, C, nullptr, K, ldB, blockIdx.y * 128,
                 ldC, blockIdx.y * 128);
}

__global__ void __launch_bounds__(256, 2) tgemm_split(
    const float* __restrict__ A, int lda, const float* __restrict__ B,
    float* __restrict__ P, int kLen, int ldB, int ldC)
{
    int z = blockIdx.z;
    gemm_core<0>(A + (size_t)z * kLen, lda, blockIdx.y * 128,
                 B + (size_t)z * kLen * ldB,
                 P + (size_t)z * ROWS * ldC, nullptr,
                 kLen, ldB, blockIdx.x * 128, ldC, blockIdx.x * 128);
}

__global__ void __launch_bounds__(256, 2) tgemm_qkv_split(
    const float* __restrict__ A, const float* __restrict__ Bq,
    const float* __restrict__ Bk, const float* __restrict__ Bv, float* __restrict__ P)
{
    int bx = blockIdx.x, z = blockIdx.z;
    const float* B; int ldB, nB;
    if (bx < 16)      { B = Bq; ldB = 2048; nB = bx * 128; }
    else if (bx < 20) { B = Bk; ldB = 512;  nB = (bx - 16) * 128; }
    else              { B = Bv; ldB = 512;  nB = (bx - 20) * 128; }
    gemm_core<0>(A + (size_t)z * 512, 4096, blockIdx.y * 128,
                 B + (size_t)z * 512 * ldB,
                 P + (size_t)z * ROWS * 3072, nullptr,
                 512, ldB, nB, 3072, bx * 128);
}

__global__ void __launch_bounds__(256, 2) tgemm_gu(
    const float* __restrict__ A, const float* __restrict__ Bg,
    const float* __restrict__ Bu, float* __restrict__ C)
{
    int bx = blockIdx.x;
    const float* B = (bx < 64) ? Bg : Bu;
    int nB = (bx & 63) * 128;
    gemm_core<0>(A, 2048, blockIdx.y * 128, B, C, nullptr, 2048, INTER, nB,
                 2 * INTER, bx * 128);
}

template <bool RES>
__global__ void __launch_bounds__(256) reduce8_kernel(
    const float* __restrict__ P, const float* __restrict__ Aux,
    float* __restrict__ C, int nElems)
{
    int i = (blockIdx.x * 256 + threadIdx.x) * 4;
    if (i >= nElems) return;
    float4 r = *reinterpret_cast<const float4*>(P + i);
#pragma unroll
    for (int z = 1; z < 8; z++) {
        float4 a = *reinterpret_cast<const float4*>(P + (size_t)z * nElems + i);
        r.x += a.x; r.y += a.y; r.z += a.z; r.w += a.w;
    }
    if (RES) {
        float4 x = *reinterpret_cast<const float4*>(Aux + i);
        r.x += x.x; r.y += x.y; r.z += x.z; r.w += x.w;
    }
    *reinterpret_cast<float4*>(C + i) = r;
}

__global__ void __launch_bounds__(256) silu_mul_kernel(
    const float* __restrict__ gu, float* __restrict__ act)
{
    int i = blockIdx.x * 256 + threadIdx.x;
    int r = i >> 13, c = i & 8191;
    float g = gu[(size_t)r * (2 * INTER) + c];
    float u = gu[(size_t)r * (2 * INTER) + INTER + c];
    act[i] = (g / (1.f + expf(-g))) * u;
}

// ---------------------------------------------------------------------------
// Norm / copy / rope / gather / logsoftmax
// ---------------------------------------------------------------------------
__global__ void __launch_bounds__(256) rms_concat_kernel(
    const float* __restrict__ emb, const float* __restrict__ hs,
    const float* __restrict__ w_in, const float* __restrict__ w_hid,
    float* __restrict__ normed)
{
    const int row = blockIdx.x;
    const int tid = threadIdx.x;
    const float* x1 = emb + (size_t)row * HIDDEN;
    const float* x2 = hs + (size_t)row * HIDDEN;
    float s1 = 0.f, s2 = 0.f;
    for (int i = tid; i < HIDDEN; i += 256) {
        float a = x1[i]; s1 += a * a;
        float b = x2[i]; s2 += b * b;
    }
    float r1 = block_sum(s1);
    float r2 = block_sum(s2);
    float inv1 = rsqrtf(r1 / (float)HIDDEN + EPS);
    float inv2 = rsqrtf(r2 / (float)HIDDEN + EPS);
    float* o = normed + (size_t)row * (2 * HIDDEN);
    for (int i = tid; i < HIDDEN; i += 256) {
        o[i]          = x1[i] * inv1 * w_in[i];
        o[HIDDEN + i] = x2[i] * inv2 * w_hid[i];
    }
}

__global__ void __launch_bounds__(256) rms_kernel(
    const float* __restrict__ x, const float* __restrict__ w, float* __restrict__ y)
{
    const int row = blockIdx.x;
    const int tid = threadIdx.x;
    const float* xr = x + (size_t)row * HIDDEN;
    float s = 0.f;
    for (int i = tid; i < HIDDEN; i += 256) { float a = xr[i]; s += a * a; }
    float r = block_sum(s);
    float inv = rsqrtf(r / (float)HIDDEN + EPS);
    float* yr = y + (size_t)row * HIDDEN;
    for (int i = tid; i < HIDDEN; i += 256) yr[i] = xr[i] * inv * w[i];
}

__global__ void __launch_bounds__(256) gather_rms_kernel(
    const float* __restrict__ hs, const int* __restrict__ lt,
    const float* __restrict__ w, float* __restrict__ out_gathered,
    float* __restrict__ fn)
{
    const int row = blockIdx.x;
    const int tid = threadIdx.x;
    const int b = row >> 6;
    const int src_s = lt[row];
    const float* x = hs + ((size_t)b * SEQ + src_s) * HIDDEN;
    float s = 0.f;
    for (int i = tid; i < HIDDEN; i += 256) { float a = x[i]; s += a * a; }
    float r = block_sum(s);
    float inv = rsqrtf(r / (float)HIDDEN + EPS);
    float* og = out_gathered + (size_t)row * HIDDEN;
    float* fr = fn + (size_t)row * HIDDEN;
    for (int i = tid; i < HIDDEN; i += 256) {
        float a = x[i];
        og[i] = a;
        fr[i] = a * inv * w[i];
    }
}

__global__ void __launch_bounds__(256) copy_past_kernel(
    const float* __restrict__ past, float* __restrict__ present)
{
    const int idx = blockIdx.x * 256 + threadIdx.x;
    const int lane = idx & 31;
    const int row = idx >> 5;
    const int t = row & 2047;
    const int bch = row >> 11;
    const float4* src = reinterpret_cast<const float4*>(past) + idx;
    float4* dst = reinterpret_cast<float4*>(present) + ((size_t)bch * TTOT + t) * 32 + lane;
    *dst = *src;
}

__global__ void __launch_bounds__(64) rope_store_kernel(
    float* __restrict__ qkv, const float* __restrict__ rope,
    const int* __restrict__ pos_ids, float* __restrict__ present)
{
    const int bs = blockIdx.x;
    const int h = blockIdx.y;
    const int d = threadIdx.x;
    const int b = bs >> 6, s = bs & 63;
    const int pos = pos_ids[bs];
    const float c = rope[(size_t)pos * 128 + d];
    const float sn = rope[(size_t)pos * 128 + 64 + d];
    float* row = qkv + (size_t)bs * 3072;
    if (h < 16) {
        float* base = row + h * 128;
        float x1 = base[d], x2 = base[d + 64];
        base[d] = x1 * c - x2 * sn;
        base[d + 64] = x2 * c + x1 * sn;
    } else if (h < 20) {
        const int kh = h - 16;
        const float* base = row + 2048 + kh * 128;
        float x1 = base[d], x2 = base[d + 64];
        float* dst = present + (((size_t)(b * 2 + 0) * NKV + kh) * TTOT + PAST + s) * HDIM;
        dst[d] = x1 * c - x2 * sn;
        dst[d + 64] = x2 * c + x1 * sn;
    } else {
        const int vh = h - 20;
        const float* base = row + 2560 + vh * 128;
        float* dst = present + (((size_t)(b * 2 + 1) * NKV + vh) * TTOT + PAST + s) * HDIM;
        dst[d] = base[d];
        dst[d + 64] = base[d + 64];
    }
}

// ---------------------------------------------------------------------------
// Attention, flash-decode split: grid (128, 6). Scores: 2 queries x 4 keys
// per thread (both q and k register-reused).
// ---------------------------------------------------------------------------
#define QS_STRIDE 132
#define SC_STRIDE 65
#define ATTN_SMEM ((32 * QS_STRIDE + 64 * QS_STRIDE + 64 * QS_STRIDE + 32 * SC_STRIDE + 64) * 4)
#define ACC_CHUNK (ROWS * NQ * HDIM)
#define ML_CHUNK (ROWS * NQ * 2)
#define NCHUNK 6
#define TILES_TOTAL 33
#define TILES_PER_CHUNK 6

__global__ void __launch_bounds__(256) attn_part_kernel(
    const float* __restrict__ qkv, const float* __restrict__ kv,
    const int* __restrict__ ctx_len, float* __restrict__ pacc, float* __restrict__ pml)
{
    extern __shared__ float sm[];
    float* qs = sm;
    float* ks = qs + 32 * QS_STRIDE;
    float* vs = ks + 64 * QS_STRIDE;
    float* sc = vs + 64 * QS_STRIDE;
    float* corr = sc + 32 * SC_STRIDE;

    const int tid = threadIdx.x;
    const int blk = blockIdx.x;
    const int cz = blockIdx.y;
    const int qb = blk & 7;
    const int kvh = (blk >> 3) & 3;
    const int b = blk >> 5;

    for (int i = tid; i < 32 * 128; i += 256) {
        int ql = i >> 7, d = i & 127;
        int qid = qb * 32 + ql;
        int gi = qid >> 6, s = qid & 63;
        qs[ql * QS_STRIDE + d] =
            qkv[(size_t)(b * SEQ + s) * 3072 + (kvh * 4 + gi) * 128 + d];
    }

    float acc[16];
#pragma unroll
    for (int i = 0; i < 16; i++) acc[i] = 0.f;
    float m = -INFINITY, l = 0.f;

    const float* Kb = kv + (((size_t)(b * 2 + 0)) * NKV + kvh) * TTOT * HDIM;
    const float* Vb = kv + (((size_t)(b * 2 + 1)) * NKV + kvh) * TTOT * HDIM;
    const int ctx = ctx_len[b];

    const int ql_s = tid >> 3;
    const int qid_s = qb * 32 + ql_s;
    const int dg = (tid & 7) * 16;
    const int qp = (tid >> 4) * 2;
    const int kt4 = tid & 15;

    const int tile0 = cz * TILES_PER_CHUNK;
    const int tile1 = min(tile0 + TILES_PER_CHUNK, TILES_TOTAL);
    for (int ti = tile0; ti < tile1; ti++) {
        const int t0 = ti * 64;
        __syncthreads();
        for (int i = tid * 4; i < 64 * 128; i += 1024) {
            int r = i >> 7, d = i & 127;
            *reinterpret_cast<float4*>(&ks[r * QS_STRIDE + d]) =
                *reinterpret_cast<const float4*>(&Kb[(size_t)(t0 + r) * HDIM + d]);
            *reinterpret_cast<float4*>(&vs[r * QS_STRIDE + d]) =
                *reinterpret_cast<const float4*>(&Vb[(size_t)(t0 + r) * HDIM + d]);
        }
        __syncthreads();
        {
            const float* q0r = &qs[qp * QS_STRIDE];
            const float* q1r = &qs[(qp + 1) * QS_STRIDE];
            float dots[2][4];
#pragma unroll
            for (int qi = 0; qi < 2; qi++)
#pragma unroll
                for (int j = 0; j < 4; j++) dots[qi][j] = 0.f;
#pragma unroll 4
            for (int d = 0; d < 128; d += 4) {
                float4 q0 = *reinterpret_cast<const float4*>(&q0r[d]);
                float4 q1 = *reinterpret_cast<const float4*>(&q1r[d]);
#pragma unroll
                for (int j = 0; j < 4; j++) {
                    float4 kk = *reinterpret_cast<const float4*>(
                        &ks[(kt4 + 16 * j) * QS_STRIDE + d]);
                    dots[0][j] = fmaf(q0.x, kk.x, dots[0][j]);
                    dots[0][j] = fmaf(q0.y, kk.y, dots[0][j]);
                    dots[0][j] = fmaf(q0.z, kk.z, dots[0][j]);
                    dots[0][j] = fmaf(q0.w, kk.w, dots[0][j]);
                    dots[1][j] = fmaf(q1.x, kk.x, dots[1][j]);
                    dots[1][j] = fmaf(q1.y, kk.y, dots[1][j]);
                    dots[1][j] = fmaf(q1.z, kk.z, dots[1][j]);
                    dots[1][j] = fmaf(q1.w, kk.w, dots[1][j]);
                }
            }
#pragma unroll
            for (int qi = 0; qi < 2; qi++) {
                int ql = qp + qi;
                int sq = (qb * 32 + ql) & 63;
#pragma unroll
                for (int j = 0; j < 4; j++) {
                    int kt = kt4 + 16 * j;
                    int t = t0 + kt;
                    bool valid = (t < PAST) ? (t < ctx) : ((t - PAST) <= sq);
                    sc[ql * SC_STRIDE + kt] =
                        valid ? dots[qi][j] * 0.08838834764831845f : -INFINITY;
                }
            }
        }
        __syncthreads();
        if (tid < 32) {
            float mt = -INFINITY;
#pragma unroll 8
            for (int j = 0; j < 64; j++) mt = fmaxf(mt, sc[tid * SC_STRIDE + j]);
            float mnew = fmaxf(m, mt);
            float c, sum = 0.f;
            if (mnew == -INFINITY) {
                c = 1.f;
                for (int j = 0; j < 64; j++) sc[tid * SC_STRIDE + j] = 0.f;
            } else {
                c = __expf(m - mnew);
#pragma unroll 8
                for (int j = 0; j < 64; j++) {
                    float p = __expf(sc[tid * SC_STRIDE + j] - mnew);
                    sc[tid * SC_STRIDE + j] = p;
                    sum += p;
                }
            }
            l = l * c + sum;
            m = mnew;
            corr[tid] = c;
        }
        __syncthreads();
        {
            float c = corr[ql_s];
#pragma unroll
            for (int i = 0; i < 16; i++) acc[i] *= c;
            for (int kt = 0; kt < 64; kt++) {
                float p = sc[ql_s * SC_STRIDE + kt];
                const float* vrow = &vs[kt * QS_STRIDE + dg];
#pragma unroll
                for (int i = 0; i < 16; i += 4) {
                    float4 vv = *reinterpret_cast<const float4*>(&vrow[i]);
                    acc[i + 0] = fmaf(p, vv.x, acc[i + 0]);
                    acc[i + 1] = fmaf(p, vv.y, acc[i + 1]);
                    acc[i + 2] = fmaf(p, vv.z, acc[i + 2]);
                    acc[i + 3] = fmaf(p, vv.w, acc[i + 3]);
                }
            }
        }
    }
    if (tid < 32) {
        int qid = qb * 32 + tid;
        int gi = qid >> 6, s = qid & 63;
        int row = (b * SEQ + s) * NQ + (kvh * 4 + gi);
        pml[(size_t)cz * ML_CHUNK + row * 2 + 0] = m;
        pml[(size_t)cz * ML_CHUNK + row * 2 + 1] = l;
    }
    {
        int gi = qid_s >> 6, s = qid_s & 63;
        int row = (b * SEQ + s) * NQ + (kvh * 4 + gi);
        float* orow = pacc + (size_t)cz * ACC_CHUNK + (size_t)row * HDIM + dg;
#pragma unroll
        for (int i = 0; i < 16; i++) orow[i] = acc[i];
    }
}

__global__ void __launch_bounds__(128) attn_merge_kernel(
    const float* __restrict__ pacc, const float* __restrict__ pml,
    float* __restrict__ out)
{
    const int row = blockIdx.x;
    const int d = threadIdx.x;
    float mv[NCHUNK], lv[NCHUNK];
    float mg = -INFINITY;
#pragma unroll
    for (int z = 0; z < NCHUNK; z++) {
        mv[z] = pml[(size_t)z * ML_CHUNK + row * 2 + 0];
        lv[z] = pml[(size_t)z * ML_CHUNK + row * 2 + 1];
        mg = fmaxf(mg, mv[z]);
    }
    float L = 0.f, a = 0.f;
    size_t o = (size_t)row * HDIM + d;
#pragma unroll
    for (int z = 0; z < NCHUNK; z++) {
        float w = __expf(mv[z] - mg);
        L += lv[z] * w;
        a += pacc[(size_t)z * ACC_CHUNK + o] * w;
    }
    out[o] = a / L;
}

__global__ void __launch_bounds__(256) logsoftmax_kernel(float* __restrict__ x)
{
    const int row = blockIdx.x;
    const int tid = threadIdx.x;
    float* xr = x + (size_t)row * VOCAB;
    float mv = -INFINITY;
    for (int i = tid; i < VOCAB; i += 256) mv = fmaxf(mv, xr[i]);
    float M = block_max(mv);
    float s = 0.f;
    for (int i = tid; i < VOCAB; i += 256) s += __expf(xr[i] - M);
    float S = block_sum(s);
    float lse = M + logf(S);
    for (int i = tid; i < VOCAB; i += 256) xr[i] = xr[i] - lse;
}

// ---------------------------------------------------------------------------
// Launch
// ---------------------------------------------------------------------------
extern "C" void kernel_launch(void* const* d_in, const int* in_sizes, int n_in,
                              void* d_out, int out_size)
{
    const float* inputs_embeds = (const float*)d_in[0];
    const float* past_kv       = (const float*)d_in[1];
    const float* rope          = (const float*)d_in[2];
    const int*   ctx_len       = (const int*)d_in[3];
    const int*   last_ids      = (const int*)d_in[5];
    const float* hsi           = (const float*)d_in[6];
    const float* hsd           = (const float*)d_in[7];
    const int*   pos_id        = (const int*)d_in[8];
    const float* W_fc   = (const float*)d_in[10];
    const float* W_q    = (const float*)d_in[11];
    const float* W_k    = (const float*)d_in[12];
    const float* W_v    = (const float*)d_in[13];
    const float* W_o    = (const float*)d_in[14];
    const float* W_gate = (const float*)d_in[15];
    const float* W_up   = (const float*)d_in[16];
    const float* W_down = (const float*)d_in[17];
    const float* W_lm   = (const float*)d_in[18];
    const float* w_hidden = (const float*)d_in[19];
    const float* w_input  = (const float*)d_in[20];
    const float* w_post   = (const float*)d_in[21];
    const float* w_final  = (const float*)d_in[22];

    float* out = (float*)d_out;
    float* out_logits   = out;
    float* out_gathered = out + LOGITS_ELEMS;
    float* out_present  = out + PRESENT_OFF;

    void* p;
    cudaGetSymbolAddress(&p, g_hs);     float* hs   = (float*)p;
    cudaGetSymbolAddress(&p, g_normed); float* nrm  = (float*)p;
    cudaGetSymbolAddress(&p, g_qkv);    float* qkv  = (float*)p;
    cudaGetSymbolAddress(&p, g_attn);   float* attnb= (float*)p;
    cudaGetSymbolAddress(&p, g_hn);     float* hn   = (float*)p;
    cudaGetSymbolAddress(&p, g_gu);     float* gu   = (float*)p;
    cudaGetSymbolAddress(&p, g_act);    float* actb = (float*)p;
    cudaGetSymbolAddress(&p, g_fn);     float* fnb  = (float*)p;
    cudaGetSymbolAddress(&p, g_part);   float* part = (float*)p;
    cudaGetSymbolAddress(&p, g_ml);     float* ml   = (float*)p;

    cudaFuncSetAttribute(attn_part_kernel, cudaFuncAttributeMaxDynamicSharedMemorySize, ATTN_SMEM);
    cudaFuncSetAttribute(tgemm<0>, cudaFuncAttributeMaxDynamicSharedMemorySize, GSMEM);
    cudaFuncSetAttribute(tgemm_lm, cudaFuncAttributeMaxDynamicSharedMemorySize, GSMEM);
    cudaFuncSetAttribute(tgemm_split, cudaFuncAttributeMaxDynamicSharedMemorySize, GSMEM);
    cudaFuncSetAttribute(tgemm_qkv_split, cudaFuncAttributeMaxDynamicSharedMemorySize, GSMEM);
    cudaFuncSetAttribute(tgemm_gu, cudaFuncAttributeMaxDynamicSharedMemorySize, GSMEM);

    // 1. hs = draft + hsi @ W_fc (split-K 8: 256 blocks)
    tgemm_split<<<dim3(16, 2, 8), 256, GSMEM>>>(hsi, 6144, W_fc, part, 768, HIDDEN, HIDDEN);
    reduce8_kernel<true><<<512, 256>>>(part, hsd, hs, ROWS * HIDDEN);
    // 2. normed
    rms_concat_kernel<<<ROWS, 256>>>(inputs_embeds, hs, w_input, w_hidden, nrm);
    // 3. fused qkv (split-K 8: 384 blocks)
    tgemm_qkv_split<<<dim3(24, 2, 8), 256, GSMEM>>>(nrm, W_q, W_k, W_v, part);
    reduce8_kernel<false><<<768, 256>>>(part, nullptr, qkv, ROWS * 3072);
    // 4. present
    copy_past_kernel<<<8192, 256>>>(past_kv, out_present);
    rope_store_kernel<<<dim3(256, 24), 64>>>(qkv, rope, pos_id, out_present);
    // 5. attention (flash-decode over 6 chunks)
    attn_part_kernel<<<dim3(128, NCHUNK), 256, ATTN_SMEM>>>(qkv, out_present, ctx_len, part, ml);
    attn_merge_kernel<<<4096, 128>>>(part, ml, attnb);
    // 6. hs += attn @ W_o (split-K 8)
    tgemm_split<<<dim3(16, 2, 8), 256, GSMEM>>>(attnb, 2048, W_o, part, 256, HIDDEN, HIDDEN);
    reduce8_kernel<true><<<512, 256>>>(part, hs, hs, ROWS * HIDDEN);
    // 7. MLP
    rms_kernel<<<ROWS, 256>>>(hs, w_post, hn);
    tgemm_gu<<<dim3(128, 2), 256, GSMEM>>>(hn, W_gate, W_up, gu);
    silu_mul_kernel<<<8192, 256>>>(gu, actb);
    tgemm_split<<<dim3(16, 2, 8), 256, GSMEM>>>(actb, INTER, W_down, part, 1024, HIDDEN, HIDDEN);
    reduce8_kernel<true><<<512, 256>>>(part, hs, hs, ROWS * HIDDEN);
    // 8. gather + final norm
    gather_rms_kernel<<<ROWS, 256>>>(hs, last_ids, w_final, out_gathered, fnb);
    // 9. LM head + log_softmax
    tgemm_lm<<<dim3(2, 250), 256, GSMEM>>>(fnb, W_lm, out_logits, 2048, VOCAB, VOCAB);
    logsoftmax_kernel<<<ROWS, 256>>>(out_logits);
}

// round 16
// speedup vs baseline: 1.0241x; 1.0241x over previous
#include <cuda_runtime.h>
#include <cuda_fp16.h>
#include <math.h>
#include <stdint.h>

#define BATCH 4
#define SEQ 64
#define PAST 2048
#define TTOT 2112
#define HIDDEN 2048
#define NQ 16
#define NKV 4
#define HDIM 128
#define INTER 8192
#define VOCAB 32000
#define ROWS 256
#define EPS 1e-6f

#define LOGITS_ELEMS (ROWS * VOCAB)
#define GATHERED_ELEMS (ROWS * HIDDEN)
#define PRESENT_OFF (LOGITS_ELEMS + GATHERED_ELEMS)

// ---------------------------------------------------------------------------
// Scratch (device globals)
// ---------------------------------------------------------------------------
__device__ float g_hs[ROWS * HIDDEN];
__device__ float g_normed[ROWS * 2 * HIDDEN];
__device__ float g_qkv[ROWS * 3072];
__device__ float g_attn[ROWS * NQ * HDIM];
__device__ float g_hn[ROWS * HIDDEN];
__device__ float g_gu[ROWS * 2 * INTER];
__device__ float g_act[ROWS * INTER];
__device__ float g_fn[ROWS * HIDDEN];
__device__ float g_part[8 * ROWS * 3072];
__device__ float g_ml[6 * ROWS * NQ * 2];

// ---------------------------------------------------------------------------
// Helpers
// ---------------------------------------------------------------------------
__device__ __forceinline__ uint32_t smem_u32(const void* p) {
    uint32_t a;
    asm("{ .reg .u64 t; cvta.to.shared.u64 t, %1; cvt.u32.u64 %0, t; }"
        : "=r"(a) : "l"(p));
    return a;
}
__device__ __forceinline__ uint32_t f2h2(float lo, float hi) {
    uint32_t r;
    asm("cvt.rn.f16x2.f32 %0, %1, %2;" : "=r"(r) : "f"(hi), "f"(lo));
    return r;
}
__device__ __forceinline__ void ldsm_x4(uint32_t* r, uint32_t addr) {
    asm volatile("ldmatrix.sync.aligned.m8n8.x4.shared.b16 {%0,%1,%2,%3}, [%4];"
                 : "=r"(r[0]), "=r"(r[1]), "=r"(r[2]), "=r"(r[3]) : "r"(addr));
}
__device__ __forceinline__ void ldsm_x2t(uint32_t* r, uint32_t addr) {
    asm volatile("ldmatrix.sync.aligned.m8n8.x2.trans.shared.b16 {%0,%1}, [%2];"
                 : "=r"(r[0]), "=r"(r[1]) : "r"(addr));
}
__device__ __forceinline__ void mma_f16(float* c, const uint32_t* a, const uint32_t* b) {
    asm volatile(
        "mma.sync.aligned.m16n8k16.row.col.f32.f16.f16.f32 "
        "{%0,%1,%2,%3}, {%4,%5,%6,%7}, {%8,%9}, {%0,%1,%2,%3};"
        : "+f"(c[0]), "+f"(c[1]), "+f"(c[2]), "+f"(c[3])
        : "r"(a[0]), "r"(a[1]), "r"(a[2]), "r"(a[3]), "r"(b[0]), "r"(b[1]));
}

__device__ __forceinline__ float block_sum(float v) {
    __shared__ float sh[8];
    __shared__ float total;
    int tid = threadIdx.x;
#pragma unroll
    for (int o = 16; o > 0; o >>= 1) v += __shfl_xor_sync(0xffffffffu, v, o);
    if ((tid & 31) == 0) sh[tid >> 5] = v;
    __syncthreads();
    if (tid == 0) {
        float s = 0.f;
#pragma unroll
        for (int i = 0; i < 8; i++) s += sh[i];
        total = s;
    }
    __syncthreads();
    float r = total;
    __syncthreads();
    return r;
}
__device__ __forceinline__ float block_max(float v) {
    __shared__ float sh[8];
    __shared__ float total;
    int tid = threadIdx.x;
#pragma unroll
    for (int o = 16; o > 0; o >>= 1) v = fmaxf(v, __shfl_xor_sync(0xffffffffu, v, o));
    if ((tid & 31) == 0) sh[tid >> 5] = v;
    __syncthreads();
    if (tid == 0) {
        float s = -INFINITY;
#pragma unroll
        for (int i = 0; i < 8; i++) s = fmaxf(s, sh[i]);
        total = s;
    }
    __syncthreads();
    float r = total;
    __syncthreads();
    return r;
}

// ---------------------------------------------------------------------------
// fp16 GEMM core (R13 proven): 128x128 C tile, 256 threads, m16n8k16 + ldmatrix.
// A smem: [128 rows][40 halves] (80B stride). B smem: [32 k][136 halves].
// 2-stage double buffer; producer LDG.128 fp32 -> cvt f16x2 -> STS.64.
// ---------------------------------------------------------------------------
#define A_BYTES (128 * 80)
#define B_BYTES (32 * 272)
#define STAGE_B (A_BYTES + B_BYTES)
#define GSMEM (2 * STAGE_B)

template <int EPI>
__device__ __forceinline__ void gemm_core(
    const float* __restrict__ A, int lda, int mBase,
    const float* __restrict__ B,
    float* __restrict__ C, const float* __restrict__ Aux,
    int kLen, int ldB, int nB, int ldC, int nC)
{
    extern __shared__ char smc[];
    const uint32_t smBase = smem_u32(smc);

    const int tid = threadIdx.x;
    const int lane = tid & 31;
    const int wid = tid >> 5;
    const int warpM = wid & 1;
    const int warpN = wid >> 1;
    const int gid = lane >> 2;
    const int tig = lane & 3;

    float acc[4][4][4];
#pragma unroll
    for (int a = 0; a < 4; a++)
#pragma unroll
        for (int b = 0; b < 4; b++)
#pragma unroll
            for (int c = 0; c < 4; c++) acc[a][b][c] = 0.f;

    int aRow[4], aKc[4], bKr[4], bNc[4];
#pragma unroll
    for (int i = 0; i < 4; i++) {
        int fi = tid + 256 * i;
        aRow[i] = fi >> 3;  aKc[i] = (fi & 7) << 2;
        bKr[i] = fi >> 5;   bNc[i] = (fi & 31) << 2;
    }

    const uint32_t aLane = smBase +
        (uint32_t)((warpM * 64 + (lane & 15)) * 80 + ((lane >> 4) << 4));
    const uint32_t bLane = smBase + A_BYTES +
        (uint32_t)((lane & 15) * 272 + warpN * 64);

    const int nStg = kLen >> 5;
    float4 aR[4], bR[4];

#pragma unroll
    for (int j = 0; j < 4; j++) {
        aR[j] = *(const float4*)(A + (size_t)(mBase + aRow[j]) * lda + aKc[j]);
        bR[j] = *(const float4*)(B + (size_t)bKr[j] * ldB + nB + bNc[j]);
    }
#pragma unroll
    for (int j = 0; j < 4; j++) {
        uint2 ha = make_uint2(f2h2(aR[j].x, aR[j].y), f2h2(aR[j].z, aR[j].w));
        *(uint2*)(smc + aRow[j] * 80 + aKc[j] * 2) = ha;
        uint2 hb = make_uint2(f2h2(bR[j].x, bR[j].y), f2h2(bR[j].z, bR[j].w));
        *(uint2*)(smc + A_BYTES + bKr[j] * 272 + bNc[j] * 2) = hb;
    }
    __syncthreads();

    for (int i = 0; i < nStg; i++) {
        const uint32_t bufOff = (uint32_t)(i & 1) * STAGE_B;
        if (i + 1 < nStg) {
            const int k0 = (i + 1) * 32;
#pragma unroll
            for (int j = 0; j < 4; j++) {
                aR[j] = *(const float4*)(A + (size_t)(mBase + aRow[j]) * lda + k0 + aKc[j]);
                bR[j] = *(const float4*)(B + (size_t)(k0 + bKr[j]) * ldB + nB + bNc[j]);
            }
        }
#pragma unroll
        for (int g = 0; g < 2; g++) {
            uint32_t aG = aLane + bufOff + g * 32;
            uint32_t bG = bLane + bufOff + (uint32_t)g * (16 * 272);
            uint32_t bf[4][2];
#pragma unroll
            for (int nj = 0; nj < 4; nj++) ldsm_x2t(bf[nj], bG + nj * 16);
#pragma unroll
            for (int mi = 0; mi < 4; mi++) {
                uint32_t af[4];
                ldsm_x4(af, aG + mi * 1280);
#pragma unroll
                for (int nj = 0; nj < 4; nj++)
                    mma_f16(acc[mi][nj], af, bf[nj]);
            }
        }
        if (i + 1 < nStg) {
            char* dst = smc + ((i + 1) & 1) * STAGE_B;
#pragma unroll
            for (int j = 0; j < 4; j++) {
                uint2 ha = make_uint2(f2h2(aR[j].x, aR[j].y), f2h2(aR[j].z, aR[j].w));
                *(uint2*)(dst + aRow[j] * 80 + aKc[j] * 2) = ha;
                uint2 hb = make_uint2(f2h2(bR[j].x, bR[j].y), f2h2(bR[j].z, bR[j].w));
                *(uint2*)(dst + A_BYTES + bKr[j] * 272 + bNc[j] * 2) = hb;
            }
        }
        __syncthreads();
    }

#pragma unroll
    for (int mi = 0; mi < 4; mi++) {
        int row = mBase + warpM * 64 + mi * 16 + gid;
#pragma unroll
        for (int nj = 0; nj < 4; nj++) {
            int col = nC + warpN * 32 + nj * 8 + tig * 2;
            float2 v0 = make_float2(acc[mi][nj][0], acc[mi][nj][1]);
            float2 v1 = make_float2(acc[mi][nj][2], acc[mi][nj][3]);
            size_t o0 = (size_t)row * ldC + col;
            size_t o1 = (size_t)(row + 8) * ldC + col;
            if (EPI == 1) {
                float2 x0 = *reinterpret_cast<const float2*>(Aux + o0);
                float2 x1 = *reinterpret_cast<const float2*>(Aux + o1);
                v0.x += x0.x; v0.y += x0.y;
                v1.x += x1.x; v1.y += x1.y;
            }
            *reinterpret_cast<float2*>(C + o0) = v0;
            *reinterpret_cast<float2*>(C + o1) = v1;
        }
    }
}

template <int EPI>
__global__ void __launch_bounds__(256, 2) tgemm(
    const float* __restrict__ A, const float* __restrict__ B,
    float* __restrict__ C, const float* __restrict__ Aux, int K, int ldB, int ldC)
{
    gemm_core<EPI>(A, K, blockIdx.y * 128, B, C, Aux, K, ldB, blockIdx.x * 128,
                   ldC, blockIdx.x * 128);
}

// lm-head: m = blockIdx.x (2), n = blockIdx.y (250): B-tile-sharing CTAs adjacent
__global__ void __launch_bounds__(256, 2) tgemm_lm(
    const float* __restrict__ A, const float* __restrict__ B,
    float* __restrict__ C, int K, int ldB, int ldC)
{
    gemm_core<0>(A, K, blockIdx.x * 128, B, C, nullptr, K, ldB, blockIdx.y * 128,
                 ldC, blockIdx.y * 128);
}

__global__ void __launch_bounds__(256, 2) tgemm_split(
    const float* __restrict__ A, int lda, const float* __restrict__ B,
    float* __restrict__ P, int kLen, int ldB, int ldC)
{
    int z = blockIdx.z;
    gemm_core<0>(A + (size_t)z * kLen, lda, blockIdx.y * 128,
                 B + (size_t)z * kLen * ldB,
                 P + (size_t)z * ROWS * ldC, nullptr,
                 kLen, ldB, blockIdx.x * 128, ldC, blockIdx.x * 128);
}

__global__ void __launch_bounds__(256, 2) tgemm_qkv_split(
    const float* __restrict__ A, const float* __restrict__ Bq,
    const float* __restrict__ Bk, const float* __restrict__ Bv, float* __restrict__ P)
{
    int bx = blockIdx.x, z = blockIdx.z;
    const float* B; int ldB, nB;
    if (bx < 16)      { B = Bq; ldB = 2048; nB = bx * 128; }
    else if (bx < 20) { B = Bk; ldB = 512;  nB = (bx - 16) * 128; }
    else              { B = Bv; ldB = 512;  nB = (bx - 20) * 128; }
    gemm_core<0>(A + (size_t)z * 512, 4096, blockIdx.y * 128,
                 B + (size_t)z * 512 * ldB,
                 P + (size_t)z * ROWS * 3072, nullptr,
                 512, ldB, nB, 3072, bx * 128);
}

__global__ void __launch_bounds__(256, 2) tgemm_gu(
    const float* __restrict__ A, const float* __restrict__ Bg,
    const float* __restrict__ Bu, float* __restrict__ C)
{
    int bx = blockIdx.x;
    const float* B = (bx < 64) ? Bg : Bu;
    int nB = (bx & 63) * 128;
    gemm_core<0>(A, 2048, blockIdx.y * 128, B, C, nullptr, 2048, INTER, nB,
                 2 * INTER, bx * 128);
}

template <bool RES>
__global__ void __launch_bounds__(256) reduce8_kernel(
    const float* __restrict__ P, const float* __restrict__ Aux,
    float* __restrict__ C, int nElems)
{
    int i = (blockIdx.x * 256 + threadIdx.x) * 4;
    if (i >= nElems) return;
    float4 r = *reinterpret_cast<const float4*>(P + i);
#pragma unroll
    for (int z = 1; z < 8; z++) {
        float4 a = *reinterpret_cast<const float4*>(P + (size_t)z * nElems + i);
        r.x += a.x; r.y += a.y; r.z += a.z; r.w += a.w;
    }
    if (RES) {
        float4 x = *reinterpret_cast<const float4*>(Aux + i);
        r.x += x.x; r.y += x.y; r.z += x.z; r.w += x.w;
    }
    *reinterpret_cast<float4*>(C + i) = r;
}

__global__ void __launch_bounds__(256) silu_mul_kernel(
    const float* __restrict__ gu, float* __restrict__ act)
{
    int i = blockIdx.x * 256 + threadIdx.x;
    int r = i >> 13, c = i & 8191;
    float g = gu[(size_t)r * (2 * INTER) + c];
    float u = gu[(size_t)r * (2 * INTER) + INTER + c];
    act[i] = (g / (1.f + expf(-g))) * u;
}

// ---------------------------------------------------------------------------
// Norm / copy / rope / gather / logsoftmax
// ---------------------------------------------------------------------------
__global__ void __launch_bounds__(256) rms_concat_kernel(
    const float* __restrict__ emb, const float* __restrict__ hs,
    const float* __restrict__ w_in, const float* __restrict__ w_hid,
    float* __restrict__ normed)
{
    const int row = blockIdx.x;
    const int tid = threadIdx.x;
    const float* x1 = emb + (size_t)row * HIDDEN;
    const float* x2 = hs + (size_t)row * HIDDEN;
    float s1 = 0.f, s2 = 0.f;
    for (int i = tid; i < HIDDEN; i += 256) {
        float a = x1[i]; s1 += a * a;
        float b = x2[i]; s2 += b * b;
    }
    float r1 = block_sum(s1);
    float r2 = block_sum(s2);
    float inv1 = rsqrtf(r1 / (float)HIDDEN + EPS);
    float inv2 = rsqrtf(r2 / (float)HIDDEN + EPS);
    float* o = normed + (size_t)row * (2 * HIDDEN);
    for (int i = tid; i < HIDDEN; i += 256) {
        o[i]          = x1[i] * inv1 * w_in[i];
        o[HIDDEN + i] = x2[i] * inv2 * w_hid[i];
    }
}

__global__ void __launch_bounds__(256) rms_kernel(
    const float* __restrict__ x, const float* __restrict__ w, float* __restrict__ y)
{
    const int row = blockIdx.x;
    const int tid = threadIdx.x;
    const float* xr = x + (size_t)row * HIDDEN;
    float s = 0.f;
    for (int i = tid; i < HIDDEN; i += 256) { float a = xr[i]; s += a * a; }
    float r = block_sum(s);
    float inv = rsqrtf(r / (float)HIDDEN + EPS);
    float* yr = y + (size_t)row * HIDDEN;
    for (int i = tid; i < HIDDEN; i += 256) yr[i] = xr[i] * inv * w[i];
}

__global__ void __launch_bounds__(256) gather_rms_kernel(
    const float* __restrict__ hs, const int* __restrict__ lt,
    const float* __restrict__ w, float* __restrict__ out_gathered,
    float* __restrict__ fn)
{
    const int row = blockIdx.x;
    const int tid = threadIdx.x;
    const int b = row >> 6;
    const int src_s = lt[row];
    const float* x = hs + ((size_t)b * SEQ + src_s) * HIDDEN;
    float s = 0.f;
    for (int i = tid; i < HIDDEN; i += 256) { float a = x[i]; s += a * a; }
    float r = block_sum(s);
    float inv = rsqrtf(r / (float)HIDDEN + EPS);
    float* og = out_gathered + (size_t)row * HIDDEN;
    float* fr = fn + (size_t)row * HIDDEN;
    for (int i = tid; i < HIDDEN; i += 256) {
        float a = x[i];
        og[i] = a;
        fr[i] = a * inv * w[i];
    }
}

__global__ void __launch_bounds__(256) copy_past_kernel(
    const float* __restrict__ past, float* __restrict__ present)
{
    const int idx = blockIdx.x * 256 + threadIdx.x;
    const int lane = idx & 31;
    const int row = idx >> 5;
    const int t = row & 2047;
    const int bch = row >> 11;
    const float4* src = reinterpret_cast<const float4*>(past) + idx;
    float4* dst = reinterpret_cast<float4*>(present) + ((size_t)bch * TTOT + t) * 32 + lane;
    *dst = *src;
}

__global__ void __launch_bounds__(64) rope_store_kernel(
    float* __restrict__ qkv, const float* __restrict__ rope,
    const int* __restrict__ pos_ids, float* __restrict__ present)
{
    const int bs = blockIdx.x;
    const int h = blockIdx.y;
    const int d = threadIdx.x;
    const int b = bs >> 6, s = bs & 63;
    const int pos = pos_ids[bs];
    const float c = rope[(size_t)pos * 128 + d];
    const float sn = rope[(size_t)pos * 128 + 64 + d];
    float* row = qkv + (size_t)bs * 3072;
    if (h < 16) {
        float* base = row + h * 128;
        float x1 = base[d], x2 = base[d + 64];
        base[d] = x1 * c - x2 * sn;
        base[d + 64] = x2 * c + x1 * sn;
    } else if (h < 20) {
        const int kh = h - 16;
        const float* base = row + 2048 + kh * 128;
        float x1 = base[d], x2 = base[d + 64];
        float* dst = present + (((size_t)(b * 2 + 0) * NKV + kh) * TTOT + PAST + s) * HDIM;
        dst[d] = x1 * c - x2 * sn;
        dst[d + 64] = x2 * c + x1 * sn;
    } else {
        const int vh = h - 20;
        const float* base = row + 2560 + vh * 128;
        float* dst = present + (((size_t)(b * 2 + 1) * NKV + vh) * TTOT + PAST + s) * HDIM;
        dst[d] = base[d];
        dst[d + 64] = base[d + 64];
    }
}

// ---------------------------------------------------------------------------
// Attention, flash-decode split: grid (128, 6). R13 scores (1q x 8k, q-reuse);
// AV loop with float4-vectorized p loads (SC_STRIDE 68, 4-aligned rows).
// ---------------------------------------------------------------------------
#define QS_STRIDE 132
#define SC_STRIDE 68
#define ATTN_SMEM ((32 * QS_STRIDE + 64 * QS_STRIDE + 64 * QS_STRIDE + 32 * SC_STRIDE + 64) * 4)
#define ACC_CHUNK (ROWS * NQ * HDIM)
#define ML_CHUNK (ROWS * NQ * 2)
#define NCHUNK 6
#define TILES_TOTAL 33
#define TILES_PER_CHUNK 6

__global__ void __launch_bounds__(256) attn_part_kernel(
    const float* __restrict__ qkv, const float* __restrict__ kv,
    const int* __restrict__ ctx_len, float* __restrict__ pacc, float* __restrict__ pml)
{
    extern __shared__ float sm[];
    float* qs = sm;
    float* ks = qs + 32 * QS_STRIDE;
    float* vs = ks + 64 * QS_STRIDE;
    float* sc = vs + 64 * QS_STRIDE;
    float* corr = sc + 32 * SC_STRIDE;

    const int tid = threadIdx.x;
    const int blk = blockIdx.x;
    const int cz = blockIdx.y;
    const int qb = blk & 7;
    const int kvh = (blk >> 3) & 3;
    const int b = blk >> 5;

    for (int i = tid; i < 32 * 128; i += 256) {
        int ql = i >> 7, d = i & 127;
        int qid = qb * 32 + ql;
        int gi = qid >> 6, s = qid & 63;
        qs[ql * QS_STRIDE + d] =
            qkv[(size_t)(b * SEQ + s) * 3072 + (kvh * 4 + gi) * 128 + d];
    }

    float acc[16];
#pragma unroll
    for (int i = 0; i < 16; i++) acc[i] = 0.f;
    float m = -INFINITY, l = 0.f;

    const float* Kb = kv + (((size_t)(b * 2 + 0)) * NKV + kvh) * TTOT * HDIM;
    const float* Vb = kv + (((size_t)(b * 2 + 1)) * NKV + kvh) * TTOT * HDIM;
    const int ctx = ctx_len[b];

    const int ql_s = tid >> 3;
    const int ktg = tid & 7;
    const int qid_s = qb * 32 + ql_s;
    const int s_q = qid_s & 63;
    const int dg = (tid & 7) * 16;

    const int tile0 = cz * TILES_PER_CHUNK;
    const int tile1 = min(tile0 + TILES_PER_CHUNK, TILES_TOTAL);
    for (int ti = tile0; ti < tile1; ti++) {
        const int t0 = ti * 64;
        __syncthreads();
        for (int i = tid * 4; i < 64 * 128; i += 1024) {
            int r = i >> 7, d = i & 127;
            *reinterpret_cast<float4*>(&ks[r * QS_STRIDE + d]) =
                *reinterpret_cast<const float4*>(&Kb[(size_t)(t0 + r) * HDIM + d]);
            *reinterpret_cast<float4*>(&vs[r * QS_STRIDE + d]) =
                *reinterpret_cast<const float4*>(&Vb[(size_t)(t0 + r) * HDIM + d]);
        }
        __syncthreads();
        // scores: 1 query x 8 keys per thread, q register-reused (R13 proven)
        {
            const float* qrow = &qs[ql_s * QS_STRIDE];
            float dots[8];
#pragma unroll
            for (int j = 0; j < 8; j++) dots[j] = 0.f;
#pragma unroll 4
            for (int d = 0; d < 128; d += 4) {
                float4 qv = *reinterpret_cast<const float4*>(&qrow[d]);
#pragma unroll
                for (int j = 0; j < 8; j++) {
                    const float* krow = &ks[(ktg + 8 * j) * QS_STRIDE + d];
                    float4 kk = *reinterpret_cast<const float4*>(krow);
                    dots[j] = fmaf(qv.x, kk.x, dots[j]);
                    dots[j] = fmaf(qv.y, kk.y, dots[j]);
                    dots[j] = fmaf(qv.z, kk.z, dots[j]);
                    dots[j] = fmaf(qv.w, kk.w, dots[j]);
                }
            }
#pragma unroll
            for (int j = 0; j < 8; j++) {
                int kt = ktg + 8 * j;
                int t = t0 + kt;
                bool valid = (t < PAST) ? (t < ctx) : ((t - PAST) <= s_q);
                sc[ql_s * SC_STRIDE + kt] =
                    valid ? dots[j] * 0.08838834764831845f : -INFINITY;
            }
        }
        __syncthreads();
        if (tid < 32) {
            float mt = -INFINITY;
#pragma unroll 8
            for (int j = 0; j < 64; j++) mt = fmaxf(mt, sc[tid * SC_STRIDE + j]);
            float mnew = fmaxf(m, mt);
            float c, sum = 0.f;
            if (mnew == -INFINITY) {
                c = 1.f;
                for (int j = 0; j < 64; j++) sc[tid * SC_STRIDE + j] = 0.f;
            } else {
                c = __expf(m - mnew);
#pragma unroll 8
                for (int j = 0; j < 64; j++) {
                    float p = __expf(sc[tid * SC_STRIDE + j] - mnew);
                    sc[tid * SC_STRIDE + j] = p;
                    sum += p;
                }
            }
            l = l * c + sum;
            m = mnew;
            corr[tid] = c;
        }
        __syncthreads();
        // AV: vectorized p loads (float4 every 4 keys), same FMA order
        {
            float c = corr[ql_s];
#pragma unroll
            for (int i = 0; i < 16; i++) acc[i] *= c;
            const float* prow = &sc[ql_s * SC_STRIDE];
            for (int kt = 0; kt < 64; kt += 4) {
                float4 p4 = *reinterpret_cast<const float4*>(&prow[kt]);
                const float* vr0 = &vs[(kt + 0) * QS_STRIDE + dg];
                const float* vr1 = &vs[(kt + 1) * QS_STRIDE + dg];
                const float* vr2 = &vs[(kt + 2) * QS_STRIDE + dg];
                const float* vr3 = &vs[(kt + 3) * QS_STRIDE + dg];
#pragma unroll
                for (int i = 0; i < 16; i += 4) {
                    float4 v0 = *reinterpret_cast<const float4*>(&vr0[i]);
                    acc[i + 0] = fmaf(p4.x, v0.x, acc[i + 0]);
                    acc[i + 1] = fmaf(p4.x, v0.y, acc[i + 1]);
                    acc[i + 2] = fmaf(p4.x, v0.z, acc[i + 2]);
                    acc[i + 3] = fmaf(p4.x, v0.w, acc[i + 3]);
                }
#pragma unroll
                for (int i = 0; i < 16; i += 4) {
                    float4 v1 = *reinterpret_cast<const float4*>(&vr1[i]);
                    acc[i + 0] = fmaf(p4.y, v1.x, acc[i + 0]);
                    acc[i + 1] = fmaf(p4.y, v1.y, acc[i + 1]);
                    acc[i + 2] = fmaf(p4.y, v1.z, acc[i + 2]);
                    acc[i + 3] = fmaf(p4.y, v1.w, acc[i + 3]);
                }
#pragma unroll
                for (int i = 0; i < 16; i += 4) {
                    float4 v2 = *reinterpret_cast<const float4*>(&vr2[i]);
                    acc[i + 0] = fmaf(p4.z, v2.x, acc[i + 0]);
                    acc[i + 1] = fmaf(p4.z, v2.y, acc[i + 1]);
                    acc[i + 2] = fmaf(p4.z, v2.z, acc[i + 2]);
                    acc[i + 3] = fmaf(p4.z, v2.w, acc[i + 3]);
                }
#pragma unroll
                for (int i = 0; i < 16; i += 4) {
                    float4 v3 = *reinterpret_cast<const float4*>(&vr3[i]);
                    acc[i + 0] = fmaf(p4.w, v3.x, acc[i + 0]);
                    acc[i + 1] = fmaf(p4.w, v3.y, acc[i + 1]);
                    acc[i + 2] = fmaf(p4.w, v3.z, acc[i + 2]);
                    acc[i + 3] = fmaf(p4.w, v3.w, acc[i + 3]);
                }
            }
        }
    }
    if (tid < 32) {
        int qid = qb * 32 + tid;
        int gi = qid >> 6, s = qid & 63;
        int row = (b * SEQ + s) * NQ + (kvh * 4 + gi);
        pml[(size_t)cz * ML_CHUNK + row * 2 + 0] = m;
        pml[(size_t)cz * ML_CHUNK + row * 2 + 1] = l;
    }
    {
        int gi = qid_s >> 6, s = qid_s & 63;
        int row = (b * SEQ + s) * NQ + (kvh * 4 + gi);
        float* orow = pacc + (size_t)cz * ACC_CHUNK + (size_t)row * HDIM + dg;
#pragma unroll
        for (int i = 0; i < 16; i++) orow[i] = acc[i];
    }
}

__global__ void __launch_bounds__(128) attn_merge_kernel(
    const float* __restrict__ pacc, const float* __restrict__ pml,
    float* __restrict__ out)
{
    const int row = blockIdx.x;
    const int d = threadIdx.x;
    float mv[NCHUNK], lv[NCHUNK];
    float mg = -INFINITY;
#pragma unroll
    for (int z = 0; z < NCHUNK; z++) {
        mv[z] = pml[(size_t)z * ML_CHUNK + row * 2 + 0];
        lv[z] = pml[(size_t)z * ML_CHUNK + row * 2 + 1];
        mg = fmaxf(mg, mv[z]);
    }
    float L = 0.f, a = 0.f;
    size_t o = (size_t)row * HDIM + d;
#pragma unroll
    for (int z = 0; z < NCHUNK; z++) {
        float w = __expf(mv[z] - mg);
        L += lv[z] * w;
        a += pacc[(size_t)z * ACC_CHUNK + o] * w;
    }
    out[o] = a / L;
}

__global__ void __launch_bounds__(256) logsoftmax_kernel(float* __restrict__ x)
{
    const int row = blockIdx.x;
    const int tid = threadIdx.x;
    float* xr = x + (size_t)row * VOCAB;
    float mv = -INFINITY;
    for (int i = tid; i < VOCAB; i += 256) mv = fmaxf(mv, xr[i]);
    float M = block_max(mv);
    float s = 0.f;
    for (int i = tid; i < VOCAB; i += 256) s += __expf(xr[i] - M);
    float S = block_sum(s);
    float lse = M + logf(S);
    for (int i = tid; i < VOCAB; i += 256) xr[i] = xr[i] - lse;
}

// ---------------------------------------------------------------------------
// Launch
// ---------------------------------------------------------------------------
extern "C" void kernel_launch(void* const* d_in, const int* in_sizes, int n_in,
                              void* d_out, int out_size)
{
    const float* inputs_embeds = (const float*)d_in[0];
    const float* past_kv       = (const float*)d_in[1];
    const float* rope          = (const float*)d_in[2];
    const int*   ctx_len       = (const int*)d_in[3];
    const int*   last_ids      = (const int*)d_in[5];
    const float* hsi           = (const float*)d_in[6];
    const float* hsd           = (const float*)d_in[7];
    const int*   pos_id        = (const int*)d_in[8];
    const float* W_fc   = (const float*)d_in[10];
    const float* W_q    = (const float*)d_in[11];
    const float* W_k    = (const float*)d_in[12];
    const float* W_v    = (const float*)d_in[13];
    const float* W_o    = (const float*)d_in[14];
    const float* W_gate = (const float*)d_in[15];
    const float* W_up   = (const float*)d_in[16];
    const float* W_down = (const float*)d_in[17];
    const float* W_lm   = (const float*)d_in[18];
    const float* w_hidden = (const float*)d_in[19];
    const float* w_input  = (const float*)d_in[20];
    const float* w_post   = (const float*)d_in[21];
    const float* w_final  = (const float*)d_in[22];

    float* out = (float*)d_out;
    float* out_logits   = out;
    float* out_gathered = out + LOGITS_ELEMS;
    float* out_present  = out + PRESENT_OFF;

    void* p;
    cudaGetSymbolAddress(&p, g_hs);     float* hs   = (float*)p;
    cudaGetSymbolAddress(&p, g_normed); float* nrm  = (float*)p;
    cudaGetSymbolAddress(&p, g_qkv);    float* qkv  = (float*)p;
    cudaGetSymbolAddress(&p, g_attn);   float* attnb= (float*)p;
    cudaGetSymbolAddress(&p, g_hn);     float* hn   = (float*)p;
    cudaGetSymbolAddress(&p, g_gu);     float* gu   = (float*)p;
    cudaGetSymbolAddress(&p, g_act);    float* actb = (float*)p;
    cudaGetSymbolAddress(&p, g_fn);     float* fnb  = (float*)p;
    cudaGetSymbolAddress(&p, g_part);   float* part = (float*)p;
    cudaGetSymbolAddress(&p, g_ml);     float* ml   = (float*)p;

    cudaFuncSetAttribute(attn_part_kernel, cudaFuncAttributeMaxDynamicSharedMemorySize, ATTN_SMEM);
    cudaFuncSetAttribute(tgemm<0>, cudaFuncAttributeMaxDynamicSharedMemorySize, GSMEM);
    cudaFuncSetAttribute(tgemm_lm, cudaFuncAttributeMaxDynamicSharedMemorySize, GSMEM);
    cudaFuncSetAttribute(tgemm_split, cudaFuncAttributeMaxDynamicSharedMemorySize, GSMEM);
    cudaFuncSetAttribute(tgemm_qkv_split, cudaFuncAttributeMaxDynamicSharedMemorySize, GSMEM);
    cudaFuncSetAttribute(tgemm_gu, cudaFuncAttributeMaxDynamicSharedMemorySize, GSMEM);

    // 1. hs = draft + hsi @ W_fc (split-K 8: 256 blocks)
    tgemm_split<<<dim3(16, 2, 8), 256, GSMEM>>>(hsi, 6144, W_fc, part, 768, HIDDEN, HIDDEN);
    reduce8_kernel<true><<<512, 256>>>(part, hsd, hs, ROWS * HIDDEN);
    // 2. normed
    rms_concat_kernel<<<ROWS, 256>>>(inputs_embeds, hs, w_input, w_hidden, nrm);
    // 3. fused qkv (split-K 8: 384 blocks)
    tgemm_qkv_split<<<dim3(24, 2, 8), 256, GSMEM>>>(nrm, W_q, W_k, W_v, part);
    reduce8_kernel<false><<<768, 256>>>(part, nullptr, qkv, ROWS * 3072);
    // 4. present
    copy_past_kernel<<<8192, 256>>>(past_kv, out_present);
    rope_store_kernel<<<dim3(256, 24), 64>>>(qkv, rope, pos_id, out_present);
    // 5. attention (flash-decode over 6 chunks)
    attn_part_kernel<<<dim3(128, NCHUNK), 256, ATTN_SMEM>>>(qkv, out_present, ctx_len, part, ml);
    attn_merge_kernel<<<4096, 128>>>(part, ml, attnb);
    // 6. hs += attn @ W_o (split-K 8)
    tgemm_split<<<dim3(16, 2, 8), 256, GSMEM>>>(attnb, 2048, W_o, part, 256, HIDDEN, HIDDEN);
    reduce8_kernel<true><<<512, 256>>>(part, hs, hs, ROWS * HIDDEN);
    // 7. MLP
    rms_kernel<<<ROWS, 256>>>(hs, w_post, hn);
    tgemm_gu<<<dim3(128, 2), 256, GSMEM>>>(hn, W_gate, W_up, gu);
    silu_mul_kernel<<<8192, 256>>>(gu, actb);
    tgemm_split<<<dim3(16, 2, 8), 256, GSMEM>>>(actb, INTER, W_down, part, 1024, HIDDEN, HIDDEN);
    reduce8_kernel<true><<<512, 256>>>(part, hs, hs, ROWS * HIDDEN);
    // 8. gather + final norm
    gather_rms_kernel<<<ROWS, 256>>>(hs, last_ids, w_final, out_gathered, fnb);
    // 9. LM head + log_softmax
    tgemm_lm<<<dim3(2, 250), 256, GSMEM>>>(fnb, W_lm, out_logits, 2048, VOCAB, VOCAB);
    logsoftmax_kernel<<<ROWS, 256>>>(out_logits);
}